// round 8
// baseline (speedup 1.0000x reference)
#include <cuda_runtime.h>

#define N_TOT 262144
#define FGN   2048
#define NBINS 2049   // 2048 query bins + overflow slot
#define NLUT  4096

// Persistent scratch (device globals are the allowed scratch mechanism).
__device__ float g_sorted_fg[FGN];
__device__ int   g_lut[NLUT];
// bins: [0]=H1_bg [1]=H2_bg [2]=S1_bg [3]=S2_bg [4]=H1_fg [5]=H2_fg [6]=S1_fg [7]=S2_fg
__device__ float g_bins[8][NBINS];

// ---------------------------------------------------------------------------
// Rank-sort the 2048 fg logits. Each 256-thread block stages all 2048 fg
// logits in smem (8KB), then its 8 warps each rank one element via
// conflict-free LDS. Also zeroes the bin arrays (device state persists
// across graph replays).
// ---------------------------------------------------------------------------
__global__ void kRank(const float4* __restrict__ logits4) {
    __shared__ float sm[FGN];
    int tid  = threadIdx.x;                       // 256
    int tidG = blockIdx.x * 256 + tid;
    if (tidG < 8 * NBINS) ((float*)g_bins)[tidG] = 0.0f;

#pragma unroll
    for (int k = 0; k < 2; k++) {
        float4 f = __ldg(&logits4[tid + k * 256]);
        int j = (tid + k * 256) * 4;
        sm[j] = f.x; sm[j + 1] = f.y; sm[j + 2] = f.z; sm[j + 3] = f.w;
    }
    __syncthreads();

    int wid = tid >> 5, lane = tid & 31;
    int gw  = blockIdx.x * 8 + wid;               // element this warp ranks
    float v = sm[gw];
    int cnt = 0;
#pragma unroll 8
    for (int j = lane; j < FGN; j += 32) {
        float u = sm[j];
        cnt += (u < v) || (u == v && j < gw);     // stable tie-break
    }
#pragma unroll
    for (int o = 16; o; o >>= 1) cnt += __shfl_xor_sync(0xffffffffu, cnt, o);
    if (lane == 0) g_sorted_fg[cnt] = v;
}

// ---------------------------------------------------------------------------
// Build a 4096-bucket LUT over [min(fg), max(fg)]:
//   LUT[j] = first index i with sorted_fg[i] >= lo + j*width.
// ---------------------------------------------------------------------------
__global__ void kLut() {
    __shared__ float s[FGN];
    int tid = threadIdx.x;                        // 1024
#pragma unroll
    for (int k = 0; k < 2; k++) s[tid + k * 1024] = g_sorted_fg[tid + k * 1024];
    __syncthreads();

    int j = blockIdx.x * 1024 + tid;              // 4 blocks -> 4096 buckets
    float lo = s[0], hi = s[FGN - 1];
    float width = (hi - lo) * (1.0f / NLUT);
    float key = lo + (float)j * width;

    int l = 0, h = FGN;
#pragma unroll
    for (int it = 0; it < 11; it++) {             // 2048 -> exactly 11 levels
        int m = (l + h) >> 1;
        if (s[m] >= key) h = m; else l = m + 1;
    }
    g_lut[j] = l;
}

// ---------------------------------------------------------------------------
// Binning pass: 4 elements per thread. Boundary searches use the LUT:
// bucket probe + short forward scan (starting one bucket early, so fp
// rounding in the bucket map can never skip a valid element).
// ---------------------------------------------------------------------------
__device__ __forceinline__ void binOne(const float* __restrict__ s,
                                       const int*   __restrict__ lut,
                                       float lo, float scale,
                                       float v, int base) {
    float x1 = v - 1.0f;
    float x2 = v + 1.0f;

    // i1 = first index with s[i] > x1
    int j1 = (int)((x1 - lo) * scale);
    j1 = min(max(j1, 1), NLUT - 1);
    int i = lut[j1 - 1];
    while (i < FGN && s[i] <= x1) i++;
    int i1 = i;

    // i2 = first index with s[i] >= x2
    int j2 = (int)((x2 - lo) * scale);
    j2 = min(max(j2, 1), NLUT - 1);
    int k = max(lut[j2 - 1], i1);
    while (k < FGN && s[k] < x2) k++;
    int i2 = k;

    float w = 0.5f * (v + 1.0f);
    atomicAdd(&g_bins[base + 0][i1], 1.0f);
    atomicAdd(&g_bins[base + 2][i1], w);
    atomicAdd(&g_bins[base + 1][i2], 1.0f);
    atomicAdd(&g_bins[base + 3][i2], w);
}

__global__ void kBins(const float4* __restrict__ logits4,
                      const int4*   __restrict__ targets4) {
    __shared__ float s[FGN];
    __shared__ int   lut[NLUT];
    for (int j = threadIdx.x; j < FGN; j += 256)  s[j]   = g_sorted_fg[j];
    for (int j = threadIdx.x; j < NLUT; j += 256) lut[j] = g_lut[j];
    __syncthreads();

    float lo    = s[0];
    float scale = (float)NLUT / (s[FGN - 1] - lo);

    int c = blockIdx.x * blockDim.x + threadIdx.x;   // chunk index (4 elems)
    if (c >= N_TOT / 4) return;
    float4 v = __ldg(&logits4[c]);
    bool isFg = (c < FGN / 4);                        // chunk entirely fg or bg

    if (isFg) {
        binOne(s, lut, lo, scale, v.x, 4);
        binOne(s, lut, lo, scale, v.y, 4);
        binOne(s, lut, lo, scale, v.z, 4);
        binOne(s, lut, lo, scale, v.w, 4);
    } else {
        int4 t = __ldg(&targets4[c]);
        if (t.x == 0) binOne(s, lut, lo, scale, v.x, 0);
        if (t.y == 0) binOne(s, lut, lo, scale, v.y, 0);
        if (t.z == 0) binOne(s, lut, lo, scale, v.z, 0);
        if (t.w == 0) binOne(s, lut, lo, scale, v.w, 0);
    }
}

// ---------------------------------------------------------------------------
// Finisher (1 block, 1024 threads): hierarchical shuffle scans, 6 barriers.
// ---------------------------------------------------------------------------
__device__ __forceinline__ float wscan_add(float p, int lane) {
    float s = p;
#pragma unroll
    for (int o = 1; o < 32; o <<= 1) {
        float n = __shfl_up_sync(0xffffffffu, s, o);
        if (lane >= o) s += n;
    }
    return s;
}
__device__ __forceinline__ float wscan_max(float p, int lane) {
    float s = p;
#pragma unroll
    for (int o = 1; o < 32; o <<= 1) {
        float n = __shfl_up_sync(0xffffffffu, s, o);
        if (lane >= o) s = fmaxf(s, n);
    }
    return s;
}

__global__ void kFinal(float* __restrict__ out) {
    __shared__ float agg[7][33];
    __shared__ float totals[8];
    int t    = threadIdx.x;
    int lane = t & 31;
    int wid  = t >> 5;          // 32 warps
    int i0 = 2 * t, i1 = 2 * t + 1;

    float h1b0 = g_bins[0][i0], h1b1 = g_bins[0][i1];
    float h2b0 = g_bins[1][i0], h2b1 = g_bins[1][i1];
    float s1b0 = g_bins[2][i0], s1b1 = g_bins[2][i1];
    float s2b0 = g_bins[3][i0], s2b1 = g_bins[3][i1];
    float h1f0 = g_bins[4][i0], h1f1 = g_bins[4][i1];
    float h2f0 = g_bins[5][i0], h2f1 = g_bins[5][i1];
    float s1f0 = g_bins[6][i0], s1f1 = g_bins[6][i1];
    float s2f0 = g_bins[7][i0], s2f1 = g_bins[7][i1];

    float a0_0 = h1b0,        a0_1 = h1b1;
    float a1_0 = h1b0 - h2b0, a1_1 = h1b1 - h2b1;
    float a2_0 = s1b0 - s2b0, a2_1 = s1b1 - s2b1;
    float a3_0 = h1f0,        a3_1 = h1f1;
    float a4_0 = h1f0 - h2f0, a4_1 = h1f1 - h2f1;
    float a5_0 = s1f0 - s2f0, a5_1 = s1f1 - s2f1;

    float sc0 = wscan_add(a0_0 + a0_1, lane);
    float sc1 = wscan_add(a1_0 + a1_1, lane);
    float sc2 = wscan_add(a2_0 + a2_1, lane);
    float sc3 = wscan_add(a3_0 + a3_1, lane);
    float sc4 = wscan_add(a4_0 + a4_1, lane);
    float sc5 = wscan_add(a5_0 + a5_1, lane);
    if (lane == 31) {
        agg[0][wid] = sc0; agg[1][wid] = sc1; agg[2][wid] = sc2;
        agg[3][wid] = sc3; agg[4][wid] = sc4; agg[5][wid] = sc5;
    }
    __syncthreads();                                   // B1

    if (wid < 6) {
        float v = agg[wid][lane];
        float s = wscan_add(v, lane);
        agg[wid][lane] = s;
        if (lane == 31) totals[wid] = s;
    }
    __syncthreads();                                   // B2

    float o0 = wid ? agg[0][wid - 1] : 0.0f;
    float o1 = wid ? agg[1][wid - 1] : 0.0f;
    float o2 = wid ? agg[2][wid - 1] : 0.0f;
    float o3 = wid ? agg[3][wid - 1] : 0.0f;
    float o4 = wid ? agg[4][wid - 1] : 0.0f;
    float o5 = wid ? agg[5][wid - 1] : 0.0f;

    float P1b_1 = o0 + sc0, P1b_0 = P1b_1 - a0_1;
    float Mb_1  = o1 + sc1, Mb_0  = Mb_1  - a1_1;
    float Sb_1  = o2 + sc2, Sb_0  = Sb_1  - a2_1;
    float P1f_1 = o3 + sc3, P1f_0 = P1f_1 - a3_1;
    float Mf_1  = o4 + sc4, Mf_0  = Mf_1  - a4_1;
    float Sf_1  = o5 + sc5, Sf_0  = Sf_1  - a5_1;

    float Nb = totals[0] + g_bins[0][FGN];
    float Na = totals[3] + g_bins[4][FGN];

    float fv0 = g_sorted_fg[i0];
    float fv1 = g_sorted_fg[i1];

    float b0 = (Nb - P1b_0) + Sb_0 - 0.5f * fv0 * Mb_0;
    float b1 = (Nb - P1b_1) + Sb_1 - 0.5f * fv1 * Mb_1;
    float A0 = (Na - P1f_0) + Sf_0 - 0.5f * fv0 * Mf_0 + 0.5f;
    float A1 = (Na - P1f_1) + Sf_1 - 0.5f * fv1 * Mf_1 + 0.5f;
    float cur0 = A0 / (A0 + b0);
    float cur1 = A1 / (A1 + b1);

    float pm = fmaxf(cur0, cur1);
    float sm = wscan_max(pm, lane);
    if (lane == 31) agg[6][wid] = sm;
    __syncthreads();                                   // B3
    if (wid == 0) {
        float v = agg[6][lane];
        agg[6][lane] = wscan_max(v, lane);
    }
    __syncthreads();                                   // B4

    float offm = wid ? agg[6][wid - 1] : 0.0f;
    float prevInWarp = __shfl_up_sync(0xffffffffu, sm, 1);
    float warpExcl = (lane == 0) ? 0.0f : prevInWarp;
    float base = fmaxf(offm, warpExcl);
    float m0 = fmaxf(base, cur0);
    float m1 = fmaxf(m0, cur1);

    __syncthreads();                                   // B5

    float sl = m0 + m1;
#pragma unroll
    for (int o = 16; o; o >>= 1) sl += __shfl_xor_sync(0xffffffffu, sl, o);
    if (lane == 0) agg[6][wid] = sl;
    __syncthreads();                                   // B6
    if (wid == 0) {
        float v = agg[6][lane];
#pragma unroll
        for (int o = 16; o; o >>= 1) v += __shfl_xor_sync(0xffffffffu, v, o);
        if (lane == 0) out[0] = 1.0f - v / (float)FGN;
    }
}

// ---------------------------------------------------------------------------
extern "C" void kernel_launch(void* const* d_in, const int* in_sizes, int n_in,
                              void* d_out, int out_size) {
    const float* logits  = (const float*)d_in[0];
    const int*   targets = (const int*)d_in[1];
    float*       out     = (float*)d_out;

    kRank<<<256, 256>>>((const float4*)logits);
    kLut<<<4, 1024>>>();
    kBins<<<(N_TOT / 4) / 256, 256>>>((const float4*)logits, (const int4*)targets);
    kFinal<<<1, 1024>>>(out);
}

// round 12
// speedup vs baseline: 1.6411x; 1.6411x over previous
#include <cuda_runtime.h>

#define N_TOT 262144
#define FGN   2048
#define NBINS 2049   // 2048 query bins + overflow slot

// Persistent scratch (device globals are the allowed scratch mechanism).
__device__ float g_sorted_fg[FGN];
// Packed bins: [0]=bg@i1 [1]=bg@i2 [2]=fg@i1 [3]=fg@i2.
// Each u64 accumulates (count << 48) | fixedpoint(w + 4, 2^20).
// Bin k stored at bit-reversed position rev11(k) to spread hot adjacent bins
// across L2 partitions; overflow bin k==2048 stays at slot 2048.
__device__ unsigned long long g_pk[4][NBINS];

#define WSCALE 1048576.0f          // 2^20
#define WMASK  ((1ULL << 48) - 1)

__device__ __forceinline__ int rev11(int k) {
    return (int)(__brev((unsigned)k) >> 21);
}
__device__ __forceinline__ float decH(unsigned long long x) {
    return (float)(unsigned)(x >> 48);
}
__device__ __forceinline__ float decS(unsigned long long x) {
    float h = (float)(unsigned)(x >> 48);
    float m = __ull2float_rn(x & WMASK);
    return m * (1.0f / WSCALE) - 4.0f * h;
}

// ---------------------------------------------------------------------------
// Rank-sort the 2048 fg logits. Each 256-thread block stages all 2048 fg
// logits in smem, then its 8 warps each rank one element via conflict-free
// LDS. Also zeroes the packed bins (state persists across graph replays).
// ---------------------------------------------------------------------------
__global__ void kRank(const float4* __restrict__ logits4) {
    __shared__ float sm[FGN];
    int tid  = threadIdx.x;                       // 256
    int tidG = blockIdx.x * 256 + tid;
    if (tidG < 4 * NBINS) ((unsigned long long*)g_pk)[tidG] = 0ULL;

#pragma unroll
    for (int k = 0; k < 2; k++) {
        float4 f = __ldg(&logits4[tid + k * 256]);
        int j = (tid + k * 256) * 4;
        sm[j] = f.x; sm[j + 1] = f.y; sm[j + 2] = f.z; sm[j + 3] = f.w;
    }
    __syncthreads();

    int wid = tid >> 5, lane = tid & 31;
    int gw  = blockIdx.x * 8 + wid;               // element this warp ranks
    float v = sm[gw];
    int cnt = 0;
#pragma unroll 8
    for (int j = lane; j < FGN; j += 32) {
        float u = sm[j];
        cnt += (u < v) || (u == v && j < gw);     // stable tie-break
    }
#pragma unroll
    for (int o = 16; o; o >>= 1) cnt += __shfl_xor_sync(0xffffffffu, cnt, o);
    if (lane == 0) g_sorted_fg[cnt] = v;
}

// ---------------------------------------------------------------------------
// Binning pass: 4 elements per thread. Binary search for
// i1 = upper_bound(v-1), i2 = lower_bound(v+1); one packed u64 atomic per
// boundary, scattered via bit-reversal to kill L2-partition hotspots.
// ---------------------------------------------------------------------------
__device__ __forceinline__ void binOne(const float* __restrict__ s,
                                       float v, int fgSel) {
    float x1 = v - 1.0f;
    float x2 = v + 1.0f;

    // i1 = first index with s[i] > x1
    int l = 0, h = FGN;
#pragma unroll
    for (int it = 0; it < 11; it++) {
        int m = (l + h) >> 1;
        if (s[m] > x1) h = m; else l = m + 1;
        if (l >= h) break;
    }
    int i1 = l;

    // i2 = first index with s[i] >= x2 (search starts at i1)
    h = FGN;
    while (l < h) {
        int m = (l + h) >> 1;
        if (s[m] >= x2) h = m; else l = m + 1;
    }
    int i2 = l;

    float w = 0.5f * (v + 1.0f);
    unsigned long long pack = (1ULL << 48) |
        (unsigned long long)__float2ll_rn((w + 4.0f) * WSCALE);

    int p1 = (i1 < FGN) ? rev11(i1) : FGN;
    int p2 = (i2 < FGN) ? rev11(i2) : FGN;
    atomicAdd(&g_pk[fgSel + 0][p1], pack);
    atomicAdd(&g_pk[fgSel + 1][p2], pack);
}

__global__ void kBins(const float4* __restrict__ logits4,
                      const int4*   __restrict__ targets4) {
    __shared__ float s[FGN];
    for (int j = threadIdx.x; j < FGN; j += 256) s[j] = g_sorted_fg[j];
    __syncthreads();

    int c = blockIdx.x * blockDim.x + threadIdx.x;   // chunk index (4 elems)
    if (c >= N_TOT / 4) return;
    float4 v = __ldg(&logits4[c]);
    bool isFg = (c < FGN / 4);                        // chunk entirely fg or bg

    if (isFg) {
        binOne(s, v.x, 2);
        binOne(s, v.y, 2);
        binOne(s, v.z, 2);
        binOne(s, v.w, 2);
    } else {
        int4 t = __ldg(&targets4[c]);
        if (t.x == 0) binOne(s, v.x, 0);
        if (t.y == 0) binOne(s, v.y, 0);
        if (t.z == 0) binOne(s, v.z, 0);
        if (t.w == 0) binOne(s, v.w, 0);
    }
}

// ---------------------------------------------------------------------------
// Finisher (1 block, 1024 threads): decode packed bins, hierarchical
// shuffle scans (6 barriers), running-max scan, reduce -> metric.
// ---------------------------------------------------------------------------
__device__ __forceinline__ float wscan_add(float p, int lane) {
    float s = p;
#pragma unroll
    for (int o = 1; o < 32; o <<= 1) {
        float n = __shfl_up_sync(0xffffffffu, s, o);
        if (lane >= o) s += n;
    }
    return s;
}
__device__ __forceinline__ float wscan_max(float p, int lane) {
    float s = p;
#pragma unroll
    for (int o = 1; o < 32; o <<= 1) {
        float n = __shfl_up_sync(0xffffffffu, s, o);
        if (lane >= o) s = fmaxf(s, n);
    }
    return s;
}

__global__ void kFinal(float* __restrict__ out) {
    __shared__ float agg[7][33];
    __shared__ float totals[8];
    int t    = threadIdx.x;
    int lane = t & 31;
    int wid  = t >> 5;          // 32 warps
    int i0 = 2 * t, i1 = 2 * t + 1;
    int P0 = rev11(i0), P1r = rev11(i1);

    unsigned long long b1_0 = g_pk[0][P0], b1_1 = g_pk[0][P1r];
    unsigned long long b2_0 = g_pk[1][P0], b2_1 = g_pk[1][P1r];
    unsigned long long f1_0 = g_pk[2][P0], f1_1 = g_pk[2][P1r];
    unsigned long long f2_0 = g_pk[3][P0], f2_1 = g_pk[3][P1r];

    float h1b0 = decH(b1_0), h1b1 = decH(b1_1);
    float s1b0 = decS(b1_0), s1b1 = decS(b1_1);
    float h2b0 = decH(b2_0), h2b1 = decH(b2_1);
    float s2b0 = decS(b2_0), s2b1 = decS(b2_1);
    float h1f0 = decH(f1_0), h1f1 = decH(f1_1);
    float s1f0 = decS(f1_0), s1f1 = decS(f1_1);
    float h2f0 = decH(f2_0), h2f1 = decH(f2_1);
    float s2f0 = decS(f2_0), s2f1 = decS(f2_1);

    // 6 scan inputs: P1bg, Mbg, Sbg, P1fg, Mfg, Sfg
    float a0_0 = h1b0,        a0_1 = h1b1;
    float a1_0 = h1b0 - h2b0, a1_1 = h1b1 - h2b1;
    float a2_0 = s1b0 - s2b0, a2_1 = s1b1 - s2b1;
    float a3_0 = h1f0,        a3_1 = h1f1;
    float a4_0 = h1f0 - h2f0, a4_1 = h1f1 - h2f1;
    float a5_0 = s1f0 - s2f0, a5_1 = s1f1 - s2f1;

    float sc0 = wscan_add(a0_0 + a0_1, lane);
    float sc1 = wscan_add(a1_0 + a1_1, lane);
    float sc2 = wscan_add(a2_0 + a2_1, lane);
    float sc3 = wscan_add(a3_0 + a3_1, lane);
    float sc4 = wscan_add(a4_0 + a4_1, lane);
    float sc5 = wscan_add(a5_0 + a5_1, lane);
    if (lane == 31) {
        agg[0][wid] = sc0; agg[1][wid] = sc1; agg[2][wid] = sc2;
        agg[3][wid] = sc3; agg[4][wid] = sc4; agg[5][wid] = sc5;
    }
    __syncthreads();                                   // B1

    if (wid < 6) {
        float v = agg[wid][lane];
        float s = wscan_add(v, lane);
        agg[wid][lane] = s;
        if (lane == 31) totals[wid] = s;
    }
    __syncthreads();                                   // B2

    float o0 = wid ? agg[0][wid - 1] : 0.0f;
    float o1 = wid ? agg[1][wid - 1] : 0.0f;
    float o2 = wid ? agg[2][wid - 1] : 0.0f;
    float o3 = wid ? agg[3][wid - 1] : 0.0f;
    float o4 = wid ? agg[4][wid - 1] : 0.0f;
    float o5 = wid ? agg[5][wid - 1] : 0.0f;

    float P1b_1 = o0 + sc0, P1b_0 = P1b_1 - a0_1;
    float Mb_1  = o1 + sc1, Mb_0  = Mb_1  - a1_1;
    float Sb_1  = o2 + sc2, Sb_0  = Sb_1  - a2_1;
    float P1f_1 = o3 + sc3, P1f_0 = P1f_1 - a3_1;
    float Mf_1  = o4 + sc4, Mf_0  = Mf_1  - a4_1;
    float Sf_1  = o5 + sc5, Sf_0  = Sf_1  - a5_1;

    float Nb = totals[0] + decH(g_pk[0][FGN]);   // + overflow slot
    float Na = totals[3] + decH(g_pk[2][FGN]);

    float fv0 = g_sorted_fg[i0];
    float fv1 = g_sorted_fg[i1];

    float b0 = (Nb - P1b_0) + Sb_0 - 0.5f * fv0 * Mb_0;
    float b1 = (Nb - P1b_1) + Sb_1 - 0.5f * fv1 * Mb_1;
    float A0 = (Na - P1f_0) + Sf_0 - 0.5f * fv0 * Mf_0 + 0.5f;
    float A1 = (Na - P1f_1) + Sf_1 - 0.5f * fv1 * Mf_1 + 0.5f;
    float cur0 = A0 / (A0 + b0);
    float cur1 = A1 / (A1 + b1);

    // Running max over ascending-sorted queries.
    float pm = fmaxf(cur0, cur1);
    float sm = wscan_max(pm, lane);
    if (lane == 31) agg[6][wid] = sm;
    __syncthreads();                                   // B3
    if (wid == 0) {
        float v = agg[6][lane];
        agg[6][lane] = wscan_max(v, lane);
    }
    __syncthreads();                                   // B4

    float offm = wid ? agg[6][wid - 1] : 0.0f;
    float prevInWarp = __shfl_up_sync(0xffffffffu, sm, 1);
    float warpExcl = (lane == 0) ? 0.0f : prevInWarp;
    float base = fmaxf(offm, warpExcl);
    float m0 = fmaxf(base, cur0);
    float m1 = fmaxf(m0, cur1);

    __syncthreads();                                   // B5

    float sl = m0 + m1;
#pragma unroll
    for (int o = 16; o; o >>= 1) sl += __shfl_xor_sync(0xffffffffu, sl, o);
    if (lane == 0) agg[6][wid] = sl;
    __syncthreads();                                   // B6
    if (wid == 0) {
        float v = agg[6][lane];
#pragma unroll
        for (int o = 16; o; o >>= 1) v += __shfl_xor_sync(0xffffffffu, v, o);
        if (lane == 0) out[0] = 1.0f - v / (float)FGN;
    }
}

// ---------------------------------------------------------------------------
extern "C" void kernel_launch(void* const* d_in, const int* in_sizes, int n_in,
                              void* d_out, int out_size) {
    const float* logits  = (const float*)d_in[0];
    const int*   targets = (const int*)d_in[1];
    float*       out     = (float*)d_out;

    kRank<<<256, 256>>>((const float4*)logits);
    kBins<<<(N_TOT / 4) / 256, 256>>>((const float4*)logits, (const int4*)targets);
    kFinal<<<1, 1024>>>(out);
}

// round 13
// speedup vs baseline: 1.7500x; 1.0664x over previous
#include <cuda_runtime.h>

#define N_TOT 262144
#define FGN   2048
#define NBINS 2049   // 2048 query bins + overflow slot
#define NLUT  4096

// Persistent scratch (device globals are the allowed scratch mechanism).
__device__ float g_sorted_fg[FGN];
__device__ int   g_lut[NLUT];
// Packed bins: [0]=bg@i1 [1]=bg@i2 [2]=fg@i1 [3]=fg@i2.
// Each u64 accumulates (count << 48) | fixedpoint(w + 4, 2^20).
// Bin k stored at bit-reversed position rev11(k) to spread hot adjacent bins
// across L2 partitions; overflow bin k==2048 stays at slot 2048.
__device__ unsigned long long g_pk[4][NBINS];

#define WSCALE 1048576.0f          // 2^20
#define WMASK  ((1ULL << 48) - 1)

__device__ __forceinline__ int rev11(int k) {
    return (int)(__brev((unsigned)k) >> 21);
}
__device__ __forceinline__ float decH(unsigned long long x) {
    return (float)(unsigned)(x >> 48);
}
__device__ __forceinline__ float decS(unsigned long long x) {
    float h = (float)(unsigned)(x >> 48);
    float m = __ull2float_rn(x & WMASK);
    return m * (1.0f / WSCALE) - 4.0f * h;
}

// ---------------------------------------------------------------------------
// Rank-sort the 2048 fg logits. Each 256-thread block stages all 2048 fg
// logits in smem, then its 8 warps each rank one element via conflict-free
// LDS. Also zeroes the packed bins (state persists across graph replays).
// ---------------------------------------------------------------------------
__global__ void kRank(const float4* __restrict__ logits4) {
    __shared__ float sm[FGN];
    int tid  = threadIdx.x;                       // 256
    int tidG = blockIdx.x * 256 + tid;
    if (tidG < 4 * NBINS) ((unsigned long long*)g_pk)[tidG] = 0ULL;

#pragma unroll
    for (int k = 0; k < 2; k++) {
        float4 f = __ldg(&logits4[tid + k * 256]);
        int j = (tid + k * 256) * 4;
        sm[j] = f.x; sm[j + 1] = f.y; sm[j + 2] = f.z; sm[j + 3] = f.w;
    }
    __syncthreads();

    int wid = tid >> 5, lane = tid & 31;
    int gw  = blockIdx.x * 8 + wid;               // element this warp ranks
    float v = sm[gw];
    int cnt = 0;
#pragma unroll 8
    for (int j = lane; j < FGN; j += 32) {
        float u = sm[j];
        cnt += (u < v) || (u == v && j < gw);     // stable tie-break
    }
#pragma unroll
    for (int o = 16; o; o >>= 1) cnt += __shfl_xor_sync(0xffffffffu, cnt, o);
    if (lane == 0) g_sorted_fg[cnt] = v;
}

// ---------------------------------------------------------------------------
// Build a 4096-bucket LUT over [min(fg), max(fg)]:
//   LUT[j] = first index i with sorted_fg[i] >= lo + j*width.
// ---------------------------------------------------------------------------
__global__ void kLut() {
    __shared__ float s[FGN];
    int tid = threadIdx.x;                        // 1024
#pragma unroll
    for (int k = 0; k < 2; k++) s[tid + k * 1024] = g_sorted_fg[tid + k * 1024];
    __syncthreads();

    int j = blockIdx.x * 1024 + tid;              // 4 blocks -> 4096 buckets
    float lo = s[0], hi = s[FGN - 1];
    float width = (hi - lo) * (1.0f / NLUT);
    float key = lo + (float)j * width;

    int l = 0, h = FGN;
#pragma unroll
    for (int it = 0; it < 11; it++) {             // 2048 -> exactly 11 levels
        int m = (l + h) >> 1;
        if (s[m] >= key) h = m; else l = m + 1;
    }
    g_lut[j] = l;
}

// ---------------------------------------------------------------------------
// Binning pass: 2 elements per thread (float2), grid 512 CTAs. Boundary
// searches via LUT probe + short forward scan; i1 and i2 searches are fully
// independent (parallel LDS chains). One packed u64 atomic per boundary,
// bit-reversed to spread hot bins across L2 partitions.
// ---------------------------------------------------------------------------
__device__ __forceinline__ void binOne(const float* __restrict__ s,
                                       const int*   __restrict__ lut,
                                       float lo, float scale,
                                       float v, int fgSel) {
    float x1 = v - 1.0f;
    float x2 = v + 1.0f;

    // independent LUT probes (start one bucket early for fp-rounding safety)
    int j1 = (int)((x1 - lo) * scale);
    j1 = min(max(j1, 1), NLUT - 1);
    int j2 = (int)((x2 - lo) * scale);
    j2 = min(max(j2, 1), NLUT - 1);
    int i = lut[j1 - 1];
    int k = lut[j2 - 1];

    // i1 = first index with s[i] > x1
    while (i < FGN && s[i] <= x1) i++;
    // i2 = first index with s[k] >= x2
    while (k < FGN && s[k] < x2) k++;

    float w = 0.5f * (v + 1.0f);
    unsigned long long pack = (1ULL << 48) |
        (unsigned long long)__float2ll_rn((w + 4.0f) * WSCALE);

    int p1 = (i < FGN) ? rev11(i) : FGN;
    int p2 = (k < FGN) ? rev11(k) : FGN;
    atomicAdd(&g_pk[fgSel + 0][p1], pack);
    atomicAdd(&g_pk[fgSel + 1][p2], pack);
}

__global__ void kBins(const float2* __restrict__ logits2,
                      const int2*   __restrict__ targets2) {
    __shared__ float s[FGN];
    __shared__ int   lut[NLUT];
    for (int j = threadIdx.x; j < FGN; j += 256)  s[j]   = g_sorted_fg[j];
    for (int j = threadIdx.x; j < NLUT; j += 256) lut[j] = g_lut[j];
    __syncthreads();

    float lo    = s[0];
    float scale = (float)NLUT / (s[FGN - 1] - lo);

    int c = blockIdx.x * blockDim.x + threadIdx.x;   // chunk index (2 elems)
    if (c >= N_TOT / 2) return;
    float2 v = __ldg(&logits2[c]);
    bool isFg = (c < FGN / 2);                        // chunk entirely fg or bg

    if (isFg) {
        binOne(s, lut, lo, scale, v.x, 2);
        binOne(s, lut, lo, scale, v.y, 2);
    } else {
        int2 t = __ldg(&targets2[c]);
        if (t.x == 0) binOne(s, lut, lo, scale, v.x, 0);
        if (t.y == 0) binOne(s, lut, lo, scale, v.y, 0);
    }
}

// ---------------------------------------------------------------------------
// Finisher (1 block, 1024 threads): decode packed bins, hierarchical
// shuffle scans (6 barriers), running-max scan, reduce -> metric.
// ---------------------------------------------------------------------------
__device__ __forceinline__ float wscan_add(float p, int lane) {
    float s = p;
#pragma unroll
    for (int o = 1; o < 32; o <<= 1) {
        float n = __shfl_up_sync(0xffffffffu, s, o);
        if (lane >= o) s += n;
    }
    return s;
}
__device__ __forceinline__ float wscan_max(float p, int lane) {
    float s = p;
#pragma unroll
    for (int o = 1; o < 32; o <<= 1) {
        float n = __shfl_up_sync(0xffffffffu, s, o);
        if (lane >= o) s = fmaxf(s, n);
    }
    return s;
}

__global__ void kFinal(float* __restrict__ out) {
    __shared__ float agg[7][33];
    __shared__ float totals[8];
    int t    = threadIdx.x;
    int lane = t & 31;
    int wid  = t >> 5;          // 32 warps
    int i0 = 2 * t, i1 = 2 * t + 1;
    int P0 = rev11(i0), P1r = rev11(i1);

    unsigned long long b1_0 = g_pk[0][P0], b1_1 = g_pk[0][P1r];
    unsigned long long b2_0 = g_pk[1][P0], b2_1 = g_pk[1][P1r];
    unsigned long long f1_0 = g_pk[2][P0], f1_1 = g_pk[2][P1r];
    unsigned long long f2_0 = g_pk[3][P0], f2_1 = g_pk[3][P1r];

    float h1b0 = decH(b1_0), h1b1 = decH(b1_1);
    float s1b0 = decS(b1_0), s1b1 = decS(b1_1);
    float h2b0 = decH(b2_0), h2b1 = decH(b2_1);
    float s2b0 = decS(b2_0), s2b1 = decS(b2_1);
    float h1f0 = decH(f1_0), h1f1 = decH(f1_1);
    float s1f0 = decS(f1_0), s1f1 = decS(f1_1);
    float h2f0 = decH(f2_0), h2f1 = decH(f2_1);
    float s2f0 = decS(f2_0), s2f1 = decS(f2_1);

    // 6 scan inputs: P1bg, Mbg, Sbg, P1fg, Mfg, Sfg
    float a0_0 = h1b0,        a0_1 = h1b1;
    float a1_0 = h1b0 - h2b0, a1_1 = h1b1 - h2b1;
    float a2_0 = s1b0 - s2b0, a2_1 = s1b1 - s2b1;
    float a3_0 = h1f0,        a3_1 = h1f1;
    float a4_0 = h1f0 - h2f0, a4_1 = h1f1 - h2f1;
    float a5_0 = s1f0 - s2f0, a5_1 = s1f1 - s2f1;

    float sc0 = wscan_add(a0_0 + a0_1, lane);
    float sc1 = wscan_add(a1_0 + a1_1, lane);
    float sc2 = wscan_add(a2_0 + a2_1, lane);
    float sc3 = wscan_add(a3_0 + a3_1, lane);
    float sc4 = wscan_add(a4_0 + a4_1, lane);
    float sc5 = wscan_add(a5_0 + a5_1, lane);
    if (lane == 31) {
        agg[0][wid] = sc0; agg[1][wid] = sc1; agg[2][wid] = sc2;
        agg[3][wid] = sc3; agg[4][wid] = sc4; agg[5][wid] = sc5;
    }
    __syncthreads();                                   // B1

    if (wid < 6) {
        float v = agg[wid][lane];
        float s = wscan_add(v, lane);
        agg[wid][lane] = s;
        if (lane == 31) totals[wid] = s;
    }
    __syncthreads();                                   // B2

    float o0 = wid ? agg[0][wid - 1] : 0.0f;
    float o1 = wid ? agg[1][wid - 1] : 0.0f;
    float o2 = wid ? agg[2][wid - 1] : 0.0f;
    float o3 = wid ? agg[3][wid - 1] : 0.0f;
    float o4 = wid ? agg[4][wid - 1] : 0.0f;
    float o5 = wid ? agg[5][wid - 1] : 0.0f;

    float P1b_1 = o0 + sc0, P1b_0 = P1b_1 - a0_1;
    float Mb_1  = o1 + sc1, Mb_0  = Mb_1  - a1_1;
    float Sb_1  = o2 + sc2, Sb_0  = Sb_1  - a2_1;
    float P1f_1 = o3 + sc3, P1f_0 = P1f_1 - a3_1;
    float Mf_1  = o4 + sc4, Mf_0  = Mf_1  - a4_1;
    float Sf_1  = o5 + sc5, Sf_0  = Sf_1  - a5_1;

    float Nb = totals[0] + decH(g_pk[0][FGN]);   // + overflow slot
    float Na = totals[3] + decH(g_pk[2][FGN]);

    float fv0 = g_sorted_fg[i0];
    float fv1 = g_sorted_fg[i1];

    float b0 = (Nb - P1b_0) + Sb_0 - 0.5f * fv0 * Mb_0;
    float b1 = (Nb - P1b_1) + Sb_1 - 0.5f * fv1 * Mb_1;
    float A0 = (Na - P1f_0) + Sf_0 - 0.5f * fv0 * Mf_0 + 0.5f;
    float A1 = (Na - P1f_1) + Sf_1 - 0.5f * fv1 * Mf_1 + 0.5f;
    float cur0 = A0 / (A0 + b0);
    float cur1 = A1 / (A1 + b1);

    // Running max over ascending-sorted queries.
    float pm = fmaxf(cur0, cur1);
    float sm = wscan_max(pm, lane);
    if (lane == 31) agg[6][wid] = sm;
    __syncthreads();                                   // B3
    if (wid == 0) {
        float v = agg[6][lane];
        agg[6][lane] = wscan_max(v, lane);
    }
    __syncthreads();                                   // B4

    float offm = wid ? agg[6][wid - 1] : 0.0f;
    float prevInWarp = __shfl_up_sync(0xffffffffu, sm, 1);
    float warpExcl = (lane == 0) ? 0.0f : prevInWarp;
    float base = fmaxf(offm, warpExcl);
    float m0 = fmaxf(base, cur0);
    float m1 = fmaxf(m0, cur1);

    __syncthreads();                                   // B5

    float sl = m0 + m1;
#pragma unroll
    for (int o = 16; o; o >>= 1) sl += __shfl_xor_sync(0xffffffffu, sl, o);
    if (lane == 0) agg[6][wid] = sl;
    __syncthreads();                                   // B6
    if (wid == 0) {
        float v = agg[6][lane];
#pragma unroll
        for (int o = 16; o; o >>= 1) v += __shfl_xor_sync(0xffffffffu, v, o);
        if (lane == 0) out[0] = 1.0f - v / (float)FGN;
    }
}

// ---------------------------------------------------------------------------
extern "C" void kernel_launch(void* const* d_in, const int* in_sizes, int n_in,
                              void* d_out, int out_size) {
    const float* logits  = (const float*)d_in[0];
    const int*   targets = (const int*)d_in[1];
    float*       out     = (float*)d_out;

    kRank<<<256, 256>>>((const float4*)logits);
    kLut<<<4, 1024>>>();
    kBins<<<(N_TOT / 2) / 256, 256>>>((const float2*)logits, (const int2*)targets);
    kFinal<<<1, 1024>>>(out);
}